// round 9
// baseline (speedup 1.0000x reference)
#include <cuda_runtime.h>
#include <cuda_bf16.h>
#include <math.h>
#include <stdint.h>

#define NB 4
#define NT 8192
#define NC 64
#define NS 256
#define NV 256
#define NL 30
#define NTOK (NB*NT)

// ---------------- device scratch ---------------------------------------------
__device__ __nv_bfloat16 g_xh[(size_t)(NL+1)*NTOK*NC];  // per-layer x history
__device__ __nv_bfloat16 g_gates[(size_t)NL*NTOK*NC];   // [l][tok][64]
__device__ __nv_bfloat16 g_convw[NL*128*128];           // [l][fn(interleaved)][k]
__device__ __nv_bfloat16 g_resw[NL*64*64];              // [l][o][k]
__device__ __nv_bfloat16 g_skipw[NL*256*64];            // [l][v][k]
__device__ __nv_bfloat16 g_w0t[256*256];                // [v][k]
__device__ __nv_bfloat16 g_w1t[256*256];                // [v][k]
__device__ float g_cbi[NL*128];                         // interleaved conv bias
__device__ float g_skipb[NS];
__device__ float g_num;
__device__ int   g_flags[256];

// ---------------- helpers ------------------------------------------------------
__device__ __forceinline__ uint32_t s2u(const void* p){
  uint32_t a;
  asm("{ .reg .u64 t; cvta.to.shared.u64 t, %1; cvt.u32.u64 %0, t; }" : "=r"(a) : "l"(p));
  return a;
}
__device__ __forceinline__ void mma16816(float* c, uint32_t a0, uint32_t a1,
                                         uint32_t a2, uint32_t a3,
                                         uint32_t b0, uint32_t b1){
  asm volatile("mma.sync.aligned.m16n8k16.row.col.f32.bf16.bf16.f32 "
    "{%0,%1,%2,%3}, {%4,%5,%6,%7}, {%8,%9}, {%0,%1,%2,%3};"
    : "+f"(c[0]), "+f"(c[1]), "+f"(c[2]), "+f"(c[3])
    : "r"(a0), "r"(a1), "r"(a2), "r"(a3), "r"(b0), "r"(b1));
}
__device__ __forceinline__ void ldsm4(uint32_t* r, uint32_t a){
  asm volatile("ldmatrix.sync.aligned.m8n8.x4.shared.b16 {%0,%1,%2,%3}, [%4];"
    : "=r"(r[0]), "=r"(r[1]), "=r"(r[2]), "=r"(r[3]) : "r"(a));
}
__device__ __forceinline__ void cp16(uint32_t d, const void* s){
  asm volatile("cp.async.ca.shared.global [%0], [%1], 16;" :: "r"(d), "l"(s));
}
__device__ __forceinline__ void cp16g(uint32_t d, const void* s){
  asm volatile("cp.async.cg.shared.global [%0], [%1], 16;" :: "r"(d), "l"(s));
}
__device__ __forceinline__ void cp16zg(uint32_t d, const void* s, int pred){
  asm volatile("{\n .reg .pred p;\n setp.ne.b32 p, %2, 0;\n"
    " @p  cp.async.cg.shared.global [%0], [%1], 16;\n"
    " @!p cp.async.cg.shared.global [%0], [%1], 16, 0;\n}"
    :: "r"(d), "l"(s), "r"(pred));
}
#define CP_COMMIT() asm volatile("cp.async.commit_group;" ::: "memory")
#define CP_WAIT0()  asm volatile("cp.async.wait_group 0;" ::: "memory")
#define CP_WAIT1()  asm volatile("cp.async.wait_group 1;" ::: "memory")

__device__ __forceinline__ uint32_t pack2(float a, float b){
  __nv_bfloat162 t = __floats2bfloat162_rn(a, b);
  return *(uint32_t*)&t;
}
__device__ __forceinline__ float tanh_ap(float x){
  float r;
  asm("tanh.approx.f32 %0, %1;" : "=f"(r) : "f"(x));
  return r;
}
__device__ __forceinline__ int ld_acq(const int* p){
  int v;
  asm volatile("ld.acquire.gpu.global.b32 %0, [%1];" : "=r"(v) : "l"(p) : "memory");
  return v;
}
__device__ __forceinline__ void red_rel(int* p){
  asm volatile("red.release.gpu.global.add.s32 [%0], %1;" :: "l"(p), "r"(1) : "memory");
}

// ---------------- prep ----------------------------------------------------------
__global__ void prep_w_kernel(const float* __restrict__ conv_w,
                              const float* __restrict__ conv_b,
                              const float* __restrict__ res_w,
                              const float* __restrict__ skip_w,
                              const float* __restrict__ w0,
                              const float* __restrict__ w1){
  int idx = blockIdx.x*256 + threadIdx.x;
  if (idx < NL*128*128){
    // interleaved filter layout: fn=2c -> tanh col c, fn=2c+1 -> sigmoid col 64+c
    int k = idx & 127, fn = (idx>>7)&127, l = idx>>14;
    int f = (fn >> 1) + (fn & 1)*64;
    float v = (k < 64) ? conv_w[((l*2+1)*64 + k)*128 + f]
                       : conv_w[((l*2+0)*64 + (k-64))*128 + f];
    g_convw[((size_t)l*128 + fn)*128 + k] = __float2bfloat16(v);
    return;
  }
  idx -= NL*128*128;
  if (idx < NL*64*64){
    int k = idx & 63, o = (idx>>6)&63, l = idx>>12;
    g_resw[((size_t)l*64 + o)*64 + k] = __float2bfloat16(res_w[((size_t)l*64 + k)*64 + o]);
    return;
  }
  idx -= NL*64*64;
  if (idx < NL*256*64){
    int k = idx & 63, v2 = (idx>>6)&255, l = idx>>14;
    g_skipw[((size_t)l*256 + v2)*64 + k] = __float2bfloat16(skip_w[((size_t)l*64 + k)*256 + v2]);
    return;
  }
  idx -= NL*256*64;
  if (idx < 256*256){
    int k = idx & 255, v2 = idx>>8;
    g_w0t[v2*256 + k] = __float2bfloat16(w0[k*256 + v2]);
    return;
  }
  idx -= 256*256;
  if (idx < 256*256){
    int k = idx & 255, v2 = idx>>8;
    g_w1t[v2*256 + k] = __float2bfloat16(w1[k*256 + v2]);
    return;
  }
  idx -= 256*256;
  if (idx < NL*128){
    int fn = idx & 127, l = idx >> 7;
    g_cbi[idx] = conv_b[l*128 + (fn >> 1) + (fn & 1)*64];
  }
}

__global__ void prep_misc_kernel(const float* __restrict__ skip_b){
  int s = threadIdx.x;
  float a = 0.f;
  #pragma unroll 6
  for (int l = 0; l < NL; l++) a += skip_b[l*NS + s];
  g_skipb[s] = a;
  g_flags[s] = 0;
  if (s == 0) g_num = 0.f;
}

__global__ void embed_kernel(const int* __restrict__ wf, const float* __restrict__ emb){
  int tid = threadIdx.x;
  int tok = blockIdx.x*4 + (tid >> 6);
  int c   = tid & 63;
  int t   = tok & (NT-1);
  int lab = (t == 0) ? 128 : wf[tok-1];
  g_xh[(size_t)tok*NC + c] = __float2bfloat16(emb[lab*NC + c]);
}

// ---------------- fused 30-layer kernel -----------------------------------------
// smem: cbi/rb buf0 @0 (768), buf1 @768; A @1536 (128x272); W @36352 (128x272);
//       R @71168 (2 x 64x144); G @89600 (128x144)
#define LOFF_A  1536
#define LOFF_W  36352
#define LOFF_R  71168
#define LOFF_G  89600
#define LSMEM   108032
#define APITCH  272
#define RPITCH  144
#define GPITCH  144

__device__ __forceinline__ void stage_wcbi(uint32_t sbase, int l, int buf, int tid,
                                           const float* res_b){
  if (tid < 32) cp16(sbase + buf*768 + tid*16, (const char*)(g_cbi + l*128) + tid*16);
  else if (tid < 48) cp16(sbase + buf*768 + 512 + (tid-32)*16,
                          (const char*)(res_b + l*64) + (tid-32)*16);
  const char* wsrc = (const char*)(g_convw + (size_t)l*16384);
  #pragma unroll
  for (int i = 0; i < 8; i++){
    int idx = tid + i*256, row = idx >> 4, c = idx & 15;
    cp16(sbase + LOFF_W + row*APITCH + c*16, wsrc + row*256 + c*16);
  }
}

__device__ __forceinline__ void stage_r(uint32_t sbase, int l, int rbuf, int tid){
  const char* rsrc = (const char*)(g_resw + (size_t)l*4096);
  #pragma unroll
  for (int i = 0; i < 2; i++){
    int idx = tid + i*256, row = idx >> 3, c = idx & 7;
    cp16(sbase + LOFF_R + rbuf*9216 + row*RPITCH + c*16, rsrc + row*128 + c*16);
  }
}

// phase 0: rows whose source is our own tokens (row >= d) or zero-fill (t < d)
// phase 1: rows needing a neighbor CTA's xh
__device__ __forceinline__ void stage_ashift_part(uint32_t sbase, const __nv_bfloat16* xsrc,
                                                  int dL, int tok0, int tid, int phase){
  #pragma unroll
  for (int i = 0; i < 4; i++){
    int idx = tid + i*256;
    int row = idx >> 3, c = idx & 7;
    int tok = tok0 + row, t = tok & (NT-1);
    int own = (row >= dL) || (t < dL);
    if ((phase == 0) == (own != 0))
      cp16zg(sbase + LOFF_A + row*APITCH + 128 + c*16,
             (const char*)(xsrc + (long)(tok - dL)*64) + c*16, t >= dL);
  }
}

__global__ __launch_bounds__(256, 2) void layers_kernel(const float* __restrict__ res_b)
{
  extern __shared__ char sm[];
  uint32_t sbase = s2u(sm);
  const int tid = threadIdx.x, warp = tid >> 5, lane = tid & 31;
  const int l4 = lane >> 2, q = lane & 3;
  const int g = warp >> 1, h = warp & 1;   // token-group, column-half
  const int cta = blockIdx.x;
  const int tok0 = cta * 128;

  // ---- prologue: layer-0 weights + full A tile ----
  stage_wcbi(sbase, 0, 0, tid, res_b);
  stage_r(sbase, 0, 0, tid);
  {
    const char* xs = (const char*)(g_xh + (size_t)tok0*64);
    #pragma unroll
    for (int i = 0; i < 4; i++){
      int idx = tid + i*256, row = idx >> 3, c = idx & 7;
      cp16g(sbase + LOFF_A + row*APITCH + c*16, xs + row*128 + c*16);
    }
    #pragma unroll
    for (int i = 0; i < 4; i++){
      int idx = tid + i*256, row = idx >> 3, c = idx & 7;
      int tok = tok0 + row, t = tok & (NT-1);
      cp16zg(sbase + LOFF_A + row*APITCH + 128 + c*16,
             (const char*)(g_xh + (long)(tok - 1)*64) + c*16, t >= 1);
    }
  }
  CP_COMMIT();

  // fragment base addresses
  const uint32_t aA = sbase + LOFF_A + (g*32 + (lane & 15))*APITCH + ((lane >> 4) << 4);
  const uint32_t bW = sbase + LOFF_W + (h*64 + (lane & 7) + ((lane >> 4) << 3))*APITCH
                    + (((lane >> 3) & 1) << 4);
  const uint32_t aG = sbase + LOFF_G + (g*32 + (lane & 15))*GPITCH + ((lane >> 4) << 4);
  const uint32_t bR0 = sbase + LOFF_R + (h*32 + (lane & 7) + ((lane >> 4) << 3))*RPITCH
                     + (((lane >> 3) & 1) << 4);

  for (int l = 0; l < NL; l++){
    const int buf = l & 1;
    CP_WAIT0();
    __syncthreads();   // A + W + R + biases ready

    // ---- conv GEMM: 32 tok x 64 cols per warp, K=128 ----
    float acc[2][8][4];
    #pragma unroll
    for (int m = 0; m < 2; m++)
      #pragma unroll
      for (int j = 0; j < 8; j++){ acc[m][j][0]=0; acc[m][j][1]=0; acc[m][j][2]=0; acc[m][j][3]=0; }
    #pragma unroll
    for (int s = 0; s < 8; s++){
      uint32_t A0[4], A1[4];
      ldsm4(A0, aA + s*32);
      ldsm4(A1, aA + 16*APITCH + s*32);
      #pragma unroll
      for (int p = 0; p < 4; p++){
        uint32_t Bv[4];
        ldsm4(Bv, bW + p*16*APITCH + s*32);
        mma16816(acc[0][2*p],   A0[0],A0[1],A0[2],A0[3], Bv[0], Bv[1]);
        mma16816(acc[0][2*p+1], A0[0],A0[1],A0[2],A0[3], Bv[2], Bv[3]);
        mma16816(acc[1][2*p],   A1[0],A1[1],A1[2],A1[3], Bv[0], Bv[1]);
        mma16816(acc[1][2*p+1], A1[0],A1[1],A1[2],A1[3], Bv[2], Bv[3]);
      }
    }

    // ---- gate: acc pair (even,odd col) = (tanh_in, sigmoid_in) for ONE channel ----
    {
      const float* cbi = (const float*)(sm + buf*768);
      #pragma unroll
      for (int m = 0; m < 2; m++)
        #pragma unroll
        for (int j = 0; j < 8; j++){
          int c0 = h*64 + j*8 + q*2;
          float cb0 = cbi[c0], cb1 = cbi[c0+1];
          #pragma unroll
          for (int r = 0; r < 2; r++){
            float v0 = acc[m][j][2*r]   + cb0;
            float v1 = acc[m][j][2*r+1] + cb1;
            float gv = tanh_ap(v0) * fmaf(0.5f, tanh_ap(0.5f*v1), 0.5f);
            float ov = __shfl_xor_sync(0xffffffffu, gv, 1);
            if (!(q & 1)){
              int row = g*32 + m*16 + l4 + 8*r;
              *(uint32_t*)(sm + LOFF_G + row*GPITCH + c0) = pack2(gv, ov);
            }
          }
        }
    }
    __syncthreads();   // G tile complete (cross-warp channel halves)

    // prefetch next-layer W + biases (conv reads of W are done)
    if (l < NL-1){
      stage_wcbi(sbase, l+1, buf ^ 1, tid, res_b);
      CP_COMMIT();
    }

    // ---- residual GEMM: 32 tok x 32 out-cols per warp, K=64, A from G tile ----
    float r2[2][4][4];
    #pragma unroll
    for (int m = 0; m < 2; m++)
      #pragma unroll
      for (int j = 0; j < 4; j++){ r2[m][j][0]=0; r2[m][j][1]=0; r2[m][j][2]=0; r2[m][j][3]=0; }
    {
      const uint32_t bR = bR0 + (l & 1)*9216;
      #pragma unroll
      for (int s = 0; s < 4; s++){
        uint32_t A0[4], A1[4];
        ldsm4(A0, aG + s*32);
        ldsm4(A1, aG + 16*GPITCH + s*32);
        #pragma unroll
        for (int p = 0; p < 2; p++){
          uint32_t Bv[4];
          ldsm4(Bv, bR + p*16*RPITCH + s*32);
          mma16816(r2[0][2*p],   A0[0],A0[1],A0[2],A0[3], Bv[0], Bv[1]);
          mma16816(r2[0][2*p+1], A0[0],A0[1],A0[2],A0[3], Bv[2], Bv[3]);
          mma16816(r2[1][2*p],   A1[0],A1[1],A1[2],A1[3], Bv[0], Bv[1]);
          mma16816(r2[1][2*p+1], A1[0],A1[1],A1[2],A1[3], Bv[2], Bv[3]);
        }
      }
    }

    // ---- writeback in-place into A half1 (warp-private rows x cols) ----
    {
      const float* sRB = (const float*)(sm + buf*768 + 512);
      #pragma unroll
      for (int m = 0; m < 2; m++)
        #pragma unroll
        for (int j2 = 0; j2 < 4; j2++){
          int col = h*32 + j2*8 + q*2;
          float rb0 = sRB[col], rb1 = sRB[col+1];
          #pragma unroll
          for (int r = 0; r < 2; r++){
            int row = g*32 + m*16 + l4 + 8*r;
            uint32_t* ap = (uint32_t*)(sm + LOFF_A + row*APITCH + col*2);
            uint32_t xp = *ap;
            __nv_bfloat162 xb = *(__nv_bfloat162*)&xp;
            float o0 = __bfloat162float(xb.x) + r2[m][j2][2*r]   + rb0;
            float o1 = __bfloat162float(xb.y) + r2[m][j2][2*r+1] + rb1;
            *ap = pack2(o0, o1);
          }
        }
    }
    __syncthreads();   // writeback + all G reads complete

    // ---- global stores ----
    {
      char* gd = (char*)(g_gates + ((size_t)l*NTOK + tok0)*64);
      #pragma unroll
      for (int i = 0; i < 4; i++){
        int idx = tid + i*256, row = idx >> 3, c = idx & 7;
        *(uint4*)(gd + row*128 + c*16) = *(uint4*)(sm + LOFF_G + row*GPITCH + c*16);
      }
    }
    if (l < NL-1){
      char* xo = (char*)(g_xh + (size_t)(l+1)*NTOK*NC + (size_t)tok0*NC);
      #pragma unroll
      for (int i = 0; i < 4; i++){
        int idx = tid + i*256, row = idx >> 3, c = idx & 7;
        *(uint4*)(xo + row*128 + c*16) = *(uint4*)(sm + LOFF_A + row*APITCH + c*16);
      }
      stage_r(sbase, l+1, (l & 1) ^ 1, tid);
      CP_COMMIT();
      __syncthreads();   // xh STG visible CTA-wide before flag release

      const int dnext = 1 << ((l+1) % 10);
      const __nv_bfloat16* xsrc = g_xh + (size_t)(l+1)*NTOK*NC;
      stage_ashift_part(sbase, xsrc, dnext, tok0, tid, 0);
      if (tid == 0){
        red_rel(g_flags + cta);
        int step = dnext >> 7; if (step == 0) step = 1;
        int nb = cta - step;
        if (nb >= 0){
          while (ld_acq(g_flags + nb) < l + 1) __nanosleep(32);
        }
      }
      __syncthreads();   // neighbor xh ready
      stage_ashift_part(sbase, xsrc, dnext, tok0, tid, 1);
      CP_COMMIT();
    }
  }
}

// ---------------- head kernel ------------------------------------------------------
#define HOFF_SKB 0
#define HOFF_B0  1024
#define HOFF_B1  2048
#define HOFF_G0  3072
#define HOFF_WC0 21504
#define HOFF_G1  58368
#define HOFF_WC1 76800
#define HOFF_W2  3072
#define HSMEM    113664
#define WPITCH2  272

__device__ __forceinline__ void head_stage1(uint32_t sbase, int gOff, int wOff,
                                            int l, int tok0, int tid){
  const char* gs = (const char*)(g_gates + ((size_t)l*NTOK + tok0)*64);
  #pragma unroll
  for (int i = 0; i < 4; i++){
    int idx = tid + i*256, row = idx >> 3, c = idx & 7;
    cp16(sbase + gOff + row*RPITCH + c*16, gs + row*128 + c*16);
  }
  const char* ws = (const char*)(g_skipw + (size_t)l*16384);
  #pragma unroll
  for (int i = 0; i < 8; i++){
    int idx = tid + i*256, row = idx >> 3, c = idx & 7;
    cp16(sbase + wOff + row*RPITCH + c*16, ws + row*128 + c*16);
  }
  CP_COMMIT();
}

__global__ __launch_bounds__(256, 1) void head_kernel(
    const float* __restrict__ b0, const float* __restrict__ b1,
    const int* __restrict__ wf, const int* __restrict__ lens)
{
  extern __shared__ char sm[];
  uint32_t sbase = s2u(sm);
  const int tid = threadIdx.x, warp = tid >> 5, lane = tid & 31;
  const int l4 = lane >> 2, q = lane & 3;
  const int tok0 = blockIdx.x * 128;

  float* sSKB = (float*)(sm + HOFF_SKB);
  float* sB0  = (float*)(sm + HOFF_B0);
  float* sB1  = (float*)(sm + HOFF_B1);
  sSKB[tid] = g_skipb[tid];
  sB0[tid]  = b0[tid];
  sB1[tid]  = b1[tid];

  head_stage1(sbase, HOFF_G0, HOFF_WC0, 0, tok0, tid);
  head_stage1(sbase, HOFF_G1, HOFF_WC1, 1, tok0, tid);

  float acc[32][4];
  #pragma unroll
  for (int j = 0; j < 32; j++){ acc[j][0]=0; acc[j][1]=0; acc[j][2]=0; acc[j][3]=0; }

  const uint32_t aLane = (warp*16 + (lane & 15))*RPITCH + ((lane >> 4) << 4);
  const uint32_t bLane = ((lane & 7) + ((lane >> 4) << 3))*RPITCH + (((lane >> 3) & 1) << 4);

  for (int l = 0; l < NL; l++){
    int buf = l & 1;
    if (l < NL-1) CP_WAIT1(); else CP_WAIT0();
    __syncthreads();

    uint32_t aAddr = sbase + (buf ? HOFF_G1  : HOFF_G0)  + aLane;
    uint32_t bAddr = sbase + (buf ? HOFF_WC1 : HOFF_WC0) + bLane;
    #pragma unroll
    for (int s = 0; s < 4; s++){
      uint32_t A[4];
      ldsm4(A, aAddr + s*32);
      #pragma unroll
      for (int p = 0; p < 16; p++){
        uint32_t Bv[4];
        ldsm4(Bv, bAddr + p*16*RPITCH + s*32);
        mma16816(acc[2*p],   A[0], A[1], A[2], A[3], Bv[0], Bv[1]);
        mma16816(acc[2*p+1], A[0], A[1], A[2], A[3], Bv[2], Bv[3]);
      }
    }
    __syncthreads();
    if (l + 2 < NL)
      head_stage1(sbase, buf ? HOFF_G1 : HOFF_G0, buf ? HOFF_WC1 : HOFF_WC0,
                  l + 2, tok0, tid);
  }

  uint32_t P[32][2];
  #pragma unroll
  for (int j = 0; j < 32; j++){
    int c0 = j*8 + q*2;
    float s0 = sSKB[c0], s1 = sSKB[c0+1];
    P[j][0] = pack2(acc[j][0] + s0, acc[j][1] + s1);
    P[j][1] = pack2(acc[j][2] + s0, acc[j][3] + s1);
  }
  __syncthreads();

  const uint32_t bLane2 = ((lane & 7) + ((lane >> 4) << 3))*WPITCH2 + (((lane >> 3) & 1) << 4);

  // ---- phase 2: hid = relu(s @ w0^T + b0) ----
  #pragma unroll
  for (int j = 0; j < 32; j++){ acc[j][0]=0; acc[j][1]=0; acc[j][2]=0; acc[j][3]=0; }
  for (int kc = 0; kc < 2; kc++){
    {
      const char* ws = (const char*)g_w0t;
      #pragma unroll
      for (int i = 0; i < 16; i++){
        int idx = tid + i*256, row = idx >> 4, c = idx & 15;
        cp16(sbase + HOFF_W2 + row*WPITCH2 + c*16, ws + row*512 + kc*256 + c*16);
      }
      CP_COMMIT(); CP_WAIT0();
    }
    __syncthreads();
    #pragma unroll
    for (int s = 0; s < 8; s++){
      int S = kc*8 + s;
      uint32_t a0 = P[2*S][0], a1 = P[2*S][1], a2 = P[2*S+1][0], a3 = P[2*S+1][1];
      #pragma unroll
      for (int p = 0; p < 16; p++){
        uint32_t Bv[4];
        ldsm4(Bv, sbase + HOFF_W2 + bLane2 + p*16*WPITCH2 + s*32);
        mma16816(acc[2*p],   a0, a1, a2, a3, Bv[0], Bv[1]);
        mma16816(acc[2*p+1], a0, a1, a2, a3, Bv[2], Bv[3]);
      }
    }
    __syncthreads();
  }
  #pragma unroll
  for (int j = 0; j < 32; j++){
    int c0 = j*8 + q*2;
    float s0 = sB0[c0], s1 = sB0[c0+1];
    P[j][0] = pack2(fmaxf(acc[j][0] + s0, 0.f), fmaxf(acc[j][1] + s1, 0.f));
    P[j][1] = pack2(fmaxf(acc[j][2] + s0, 0.f), fmaxf(acc[j][3] + s1, 0.f));
  }

  // ---- phase 3: logits = hid @ w1^T ----
  #pragma unroll
  for (int j = 0; j < 32; j++){ acc[j][0]=0; acc[j][1]=0; acc[j][2]=0; acc[j][3]=0; }
  for (int kc = 0; kc < 2; kc++){
    {
      const char* ws = (const char*)g_w1t;
      #pragma unroll
      for (int i = 0; i < 16; i++){
        int idx = tid + i*256, row = idx >> 4, c = idx & 15;
        cp16(sbase + HOFF_W2 + row*WPITCH2 + c*16, ws + row*512 + kc*256 + c*16);
      }
      CP_COMMIT(); CP_WAIT0();
    }
    __syncthreads();
    #pragma unroll
    for (int s = 0; s < 8; s++){
      int S = kc*8 + s;
      uint32_t a0 = P[2*S][0], a1 = P[2*S][1], a2 = P[2*S+1][0], a3 = P[2*S+1][1];
      #pragma unroll
      for (int p = 0; p < 16; p++){
        uint32_t Bv[4];
        ldsm4(Bv, sbase + HOFF_W2 + bLane2 + p*16*WPITCH2 + s*32);
        mma16816(acc[2*p],   a0, a1, a2, a3, Bv[0], Bv[1]);
        mma16816(acc[2*p+1], a0, a1, a2, a3, Bv[2], Bv[3]);
      }
    }
    __syncthreads();
  }

  // ---- CE ----
  float local = 0.f;
  int tokA = tok0 + warp*16 + l4;
  #pragma unroll
  for (int r = 0; r < 2; r++){
    int tok = tokA + r*8;
    int lab = wf[tok];
    float m = -1e30f;
    #pragma unroll
    for (int j = 0; j < 32; j++){
      int c0 = j*8 + q*2;
      float v0 = acc[j][2*r]   + sB1[c0];
      float v1 = acc[j][2*r+1] + sB1[c0+1];
      m = fmaxf(m, fmaxf(v0, v1));
    }
    m = fmaxf(m, __shfl_xor_sync(0xffffffffu, m, 1));
    m = fmaxf(m, __shfl_xor_sync(0xffffffffu, m, 2));
    float s = 0.f, lv = 0.f;
    #pragma unroll
    for (int j = 0; j < 32; j++){
      int c0 = j*8 + q*2;
      float v0 = acc[j][2*r]   + sB1[c0];
      float v1 = acc[j][2*r+1] + sB1[c0+1];
      s += __expf(v0 - m) + __expf(v1 - m);
      if (lab == c0)   lv += v0;
      if (lab == c0+1) lv += v1;
    }
    s  += __shfl_xor_sync(0xffffffffu, s, 1);
    s  += __shfl_xor_sync(0xffffffffu, s, 2);
    lv += __shfl_xor_sync(0xffffffffu, lv, 1);
    lv += __shfl_xor_sync(0xffffffffu, lv, 2);
    float ce = m + logf(s) - lv;
    int t = tok & (NT-1);
    int b = tok >> 13;
    if (q == 0 && t < lens[b]) local += ce;
  }
  #pragma unroll
  for (int off = 16; off; off >>= 1)
    local += __shfl_xor_sync(0xffffffffu, local, off);
  if (lane == 0) atomicAdd(&g_num, local);
}

__global__ void finalize_kernel(const int* __restrict__ lens, float* __restrict__ out){
  float denom = 0.f;
  for (int b = 0; b < NB; b++) denom += (float)lens[b];
  out[0] = g_num / fmaxf(denom, 1.f);
}

// ---------------- launcher ----------------------------------------------------------
extern "C" void kernel_launch(void* const* d_in, const int* in_sizes, int n_in,
                              void* d_out, int out_size)
{
  const int*   wf     = (const int*)d_in[0];
  const int*   lens   = (const int*)d_in[1];
  const float* emb    = (const float*)d_in[2];
  const float* conv_w = (const float*)d_in[3];
  const float* conv_b = (const float*)d_in[4];
  const float* res_w  = (const float*)d_in[5];
  const float* res_b  = (const float*)d_in[6];
  const float* skip_w = (const float*)d_in[7];
  const float* skip_b = (const float*)d_in[8];
  const float* w0     = (const float*)d_in[9];
  const float* b0     = (const float*)d_in[10];
  const float* w1     = (const float*)d_in[11];
  const float* b1     = (const float*)d_in[12];

  cudaFuncSetAttribute(layers_kernel, cudaFuncAttributeMaxDynamicSharedMemorySize, LSMEM);
  cudaFuncSetAttribute(head_kernel,   cudaFuncAttributeMaxDynamicSharedMemorySize, HSMEM);

  prep_misc_kernel<<<1, NS>>>(skip_b);
  prep_w_kernel<<<4847, 256>>>(conv_w, conv_b, res_w, skip_w, w0, w1);
  embed_kernel<<<NTOK/4, 256>>>(wf, emb);
  layers_kernel<<<NTOK/128, 256, LSMEM>>>(res_b);
  head_kernel<<<NTOK/128, 256, HSMEM>>>(b0, b1, wf, lens);
  finalize_kernel<<<1, 1>>>(lens, (float*)d_out);
}